// round 12
// baseline (speedup 1.0000x reference)
#include <cuda_runtime.h>
#include <cstdint>

#define H    512
#define G4   2048
#define SEQL 1024
#define EMB  300
#define NCTA 64
#define TPB  256

// Scratch: 8 MB gate-precompute (transposed [t][u][gate]) + 4 MB tagged-h ring.
__device__ float g_xg4[SEQL * G4];
__device__ __align__(16) unsigned long long g_htag[SEQL * H];

// ---------------------------------------------------------------------------
// Kernel 1: xg[t][u][g] = (b_ih[r]+b_hh[r]) + sum_e emb[tok[t]][e]*W_ih[r][e],
// r = g*512+u. 64x64 tile per block, 4x4 micro-tile per thread.
// ---------------------------------------------------------------------------
#define TK 16
__global__ __launch_bounds__(256) void xgemm_kernel(
    const int* __restrict__ tokens,
    const float* __restrict__ emb,
    const float* __restrict__ Wih,
    const float* __restrict__ bih,
    const float* __restrict__ bhh)
{
    __shared__ float Ws[64][TK + 1];
    __shared__ float Xs[64][TK + 1];
    __shared__ int   toks[64];

    const int row0 = blockIdx.x * 64;
    const int t0   = blockIdx.y * 64;
    const int tid  = threadIdx.x;
    const int tx = tid & 15, ty = tid >> 4;

    if (tid < 64) toks[tid] = tokens[t0 + tid];
    __syncthreads();

    float acc[4][4];
#pragma unroll
    for (int i = 0; i < 4; i++)
#pragma unroll
        for (int j = 0; j < 4; j++) acc[i][j] = 0.f;

    const int kk = tid & 15;
    const int ib = tid >> 4;

    for (int k0 = 0; k0 < EMB; k0 += TK) {
#pragma unroll
        for (int q = 0; q < 4; q++) {
            int i = ib + q * 16;
            int e = k0 + kk;
            long widx = (long)(row0 + i) * EMB + (e < EMB ? e : EMB - 1);
            Ws[i][kk] = Wih[widx];
            Xs[i][kk] = (e < EMB) ? emb[(long)toks[i] * EMB + e] : 0.f;
        }
        __syncthreads();
#pragma unroll
        for (int k = 0; k < TK; k++) {
            float a[4], x[4];
#pragma unroll
            for (int i = 0; i < 4; i++) a[i] = Ws[tx * 4 + i][k];
#pragma unroll
            for (int j = 0; j < 4; j++) x[j] = Xs[ty * 4 + j][k];
#pragma unroll
            for (int i = 0; i < 4; i++)
#pragma unroll
                for (int j = 0; j < 4; j++)
                    acc[i][j] += a[i] * x[j];
        }
        __syncthreads();
    }

#pragma unroll
    for (int i = 0; i < 4; i++) {
        int row = row0 + tx * 4 + i;
        float bias = bih[row] + bhh[row];
        int u = row & 511, g = row >> 9;
#pragma unroll
        for (int j = 0; j < 4; j++) {
            int t = t0 + ty * 4 + j;
            g_xg4[(long)t * G4 + u * 4 + g] = acc[i][j] + bias;   // [t][u][gate]
        }
    }
}

// ---------------------------------------------------------------------------
// packed fp32x2 FMA (sm_103a; only via PTX)
// ---------------------------------------------------------------------------
__device__ __forceinline__ void ffma2(unsigned long long& d,
                                      unsigned long long a, unsigned long long b)
{
    asm("fma.rn.f32x2 %0, %1, %2, %3;" : "=l"(d) : "l"(a), "l"(b), "l"(d));
}

__device__ __forceinline__ float fast_tanh(float x)
{
    float a = fabsf(x);
    float e = __expf(-2.f * a);
    float r = __fdividef(1.f - e, 1.f + e);
    return copysignf(r, x);
}
__device__ __forceinline__ float fast_sigmoid(float x)
{
    return __fdividef(1.f, 1.f + __expf(-x));
}

// ---------------------------------------------------------------------------
// Kernel 2: persistent LSTM recurrence.
// 64 CTAs x 256 threads, lockstep (trailing barrier load-bearing per R2/R3).
// Warp w owns hidden unit u = 8b + w, computing ALL FOUR gate rows of u:
// lane covers K in [16*lane, 16*lane+16) for 4 rows -> wp[4][8],
// 8 LDS.64 + 32 ffma2 per thread (R4's data density; R7's 32-LDS layout
// cost +384 cyc/step through the smem crossbar). 4 accumulators reduce via
// 5-level xor-shfl; lane 0 holds all gate sums -> nonlinearity + tagged
// publish, parallel across all 8 warps. No gates smem, no mid barrier
// (vs R4: one fewer barrier + no gates round-trip). Unpaced tight poll
// (R4-proven).
//
// smem h layout: h[k] at f(k) = 18*(k>>4) + (k&15); lane reads 8
// contiguous u64 at float offset 18*lane (conflict-free, proven in R4).
// ---------------------------------------------------------------------------
__global__ __launch_bounds__(TPB, 1) void lstm_kernel(
    const int* __restrict__ tokens,
    const float* __restrict__ h0,
    const float* __restrict__ c0,
    const float* __restrict__ Whh,
    float* __restrict__ out)
{
    __shared__ __align__(16) float h_s[576];
    __shared__ int toks[SEQL];

    const int b    = blockIdx.x;
    const int tid  = threadIdx.x;
    const int w    = tid >> 5;
    const int lane = tid & 31;
    const int u    = b * 8 + w;          // hidden unit owned by this warp

    for (int i = tid; i < SEQL; i += TPB) toks[i] = tokens[i];

    // Weights: all 4 gate rows of unit u, K slice [16*lane, 16*lane+16).
    unsigned long long wp[4][8];
#pragma unroll
    for (int g = 0; g < 4; g++) {
        const float* wrow = Whh + (size_t)(g * H + u) * H + 16 * lane;
#pragma unroll
        for (int j = 0; j < 8; j++) {
            float2 f = *(const float2*)(wrow + 2 * j);
            unsigned long long v;
            asm("mov.b64 %0, {%1,%2};" : "=l"(v) : "f"(f.x), "f"(f.y));
            wp[g][j] = v;
        }
    }

    float c_reg = 0.f, h_last = 0.f, out_reg = 0.f;
    if (lane == 0) { c_reg = c0[u]; h_last = h0[u]; }

    unsigned long long* htag = g_htag;

    for (int t = 0; t < SEQL; t++) {
        // lane 0 prefetches this unit's 4 gate biases (1 LDG.128),
        // latency hidden behind the poll below.
        float4 xgv = make_float4(0.f, 0.f, 0.f, 0.f);
        if (lane == 0)
            xgv = *(const float4*)(g_xg4 + (size_t)t * G4 + u * 4);

        // Acquire h_{t-1} into padded smem (thread handles k0 = 2*tid, +1).
        {
            const int k0 = 2 * tid;
            float* dst = &h_s[18 * (k0 >> 4) + (k0 & 15)];
            if (t == 0) {
                *(float2*)dst = *(const float2*)(h0 + k0);
            } else {
                const unsigned long long* ptr =
                    htag + (size_t)(t - 1) * H + k0;
                unsigned long long v0, v1;
                const unsigned tag = (unsigned)t;
                do {
                    asm volatile("ld.volatile.global.v2.u64 {%0,%1},[%2];"
                                 : "=l"(v0), "=l"(v1) : "l"(ptr));
                } while ((unsigned)(v0 >> 32) != tag ||
                         (unsigned)(v1 >> 32) != tag);
                float2 hv;
                hv.x = __uint_as_float((unsigned)v0);
                hv.y = __uint_as_float((unsigned)v1);
                *(float2*)dst = hv;
            }
        }
        __syncthreads();

        // Dot: 4 gate rows x 16 K per thread; 8 LDS.64, each h pair
        // reused across the 4 rows (32 ffma2 total).
        unsigned long long a0 = 0ull, a1 = 0ull, a2 = 0ull, a3 = 0ull;
        const unsigned long long* hb =
            (const unsigned long long*)&h_s[18 * lane];
#pragma unroll
        for (int j = 0; j < 8; j++) {
            unsigned long long hv = hb[j];
            ffma2(a0, wp[0][j], hv);
            ffma2(a1, wp[1][j], hv);
            ffma2(a2, wp[2][j], hv);
            ffma2(a3, wp[3][j], hv);
        }
        float acc0, acc1, acc2, acc3;
        {
            float lo, hi;
            asm("mov.b64 {%0,%1}, %2;" : "=f"(lo), "=f"(hi) : "l"(a0)); acc0 = lo + hi;
            asm("mov.b64 {%0,%1}, %2;" : "=f"(lo), "=f"(hi) : "l"(a1)); acc1 = lo + hi;
            asm("mov.b64 {%0,%1}, %2;" : "=f"(lo), "=f"(hi) : "l"(a2)); acc2 = lo + hi;
            asm("mov.b64 {%0,%1}, %2;" : "=f"(lo), "=f"(hi) : "l"(a3)); acc3 = lo + hi;
        }
#pragma unroll
        for (int off = 16; off > 0; off >>= 1) {
            acc0 += __shfl_xor_sync(0xffffffffu, acc0, off);
            acc1 += __shfl_xor_sync(0xffffffffu, acc1, off);
            acc2 += __shfl_xor_sync(0xffffffffu, acc2, off);
            acc3 += __shfl_xor_sync(0xffffffffu, acc3, off);
        }

        // lane 0 holds all four gate sums: nonlinearity + publish, in
        // parallel across all 8 warps (no gates smem, no mid barrier).
        if (lane == 0) {
            float si = fast_sigmoid(acc0 + xgv.x);
            float sf = fast_sigmoid(acc1 + xgv.y);
            float tg = fast_tanh   (acc2 + xgv.z);
            float so = fast_sigmoid(acc3 + xgv.w);
            float c_new = sf * c_reg + si * tg;
            float h_new = so * fast_tanh(c_new);
            if (toks[t] != 1) {                 // PAD_IDX == 1
                c_reg  = c_new;
                h_last = h_new;
                out_reg = h_new;
            }
            unsigned long long v =
                ((unsigned long long)(unsigned)(t + 1) << 32) |
                (unsigned long long)__float_as_uint(h_last);
            htag[(size_t)t * H + u] = v;
        }
        __syncthreads();   // lockstep: load-bearing (R2/R3 post-mortems)
    }

    if (lane == 0) {
        out[u]         = out_reg;  // out
        out[H + u]     = h_last;   // h
        out[2 * H + u] = c_reg;    // c
    }
}

extern "C" void kernel_launch(void* const* d_in, const int* in_sizes, int n_in,
                              void* d_out, int out_size)
{
    const int*   tokens = (const int*)  d_in[0];
    const float* h0     = (const float*)d_in[1];
    const float* c0     = (const float*)d_in[2];
    const float* emb    = (const float*)d_in[3];
    const float* Wih    = (const float*)d_in[4];
    const float* Whh    = (const float*)d_in[5];
    const float* bih    = (const float*)d_in[6];
    const float* bhh    = (const float*)d_in[7];
    float* out = (float*)d_out;

    // Reset the tag buffer every launch (deterministic across graph replays).
    void* htag_ptr = nullptr;
    cudaGetSymbolAddress(&htag_ptr, g_htag);
    cudaMemsetAsync(htag_ptr, 0, sizeof(unsigned long long) * SEQL * H);

    dim3 g1(G4 / 64, SEQL / 64);
    xgemm_kernel<<<g1, 256>>>(tokens, emb, Wih, bih, bhh);
    lstm_kernel<<<NCTA, TPB>>>(tokens, h0, c0, Whh, out);
}

// round 14
// speedup vs baseline: 1.5749x; 1.5749x over previous
#include <cuda_runtime.h>
#include <cstdint>

#define H    512
#define G4   2048
#define SEQL 1024
#define EMB  300
#define NCTA 64
#define TPB  256

// Scratch: 8 MB gate-precompute (transposed [t][u][gate]) + 4 MB tagged-h ring.
__device__ float g_xg4[SEQL * G4];
__device__ __align__(16) unsigned long long g_htag[SEQL * H];

// ---------------------------------------------------------------------------
// Kernel 1: xg[t][u][g] = (b_ih[r]+b_hh[r]) + sum_e emb[tok[t]][e]*W_ih[r][e],
// r = g*512+u. 64x64 tile per block, 4x4 micro-tile per thread.
// ---------------------------------------------------------------------------
#define TK 16
__global__ __launch_bounds__(256) void xgemm_kernel(
    const int* __restrict__ tokens,
    const float* __restrict__ emb,
    const float* __restrict__ Wih,
    const float* __restrict__ bih,
    const float* __restrict__ bhh)
{
    __shared__ float Ws[64][TK + 1];
    __shared__ float Xs[64][TK + 1];
    __shared__ int   toks[64];

    const int row0 = blockIdx.x * 64;
    const int t0   = blockIdx.y * 64;
    const int tid  = threadIdx.x;
    const int tx = tid & 15, ty = tid >> 4;

    if (tid < 64) toks[tid] = tokens[t0 + tid];
    __syncthreads();

    float acc[4][4];
#pragma unroll
    for (int i = 0; i < 4; i++)
#pragma unroll
        for (int j = 0; j < 4; j++) acc[i][j] = 0.f;

    const int kk = tid & 15;
    const int ib = tid >> 4;

    for (int k0 = 0; k0 < EMB; k0 += TK) {
#pragma unroll
        for (int q = 0; q < 4; q++) {
            int i = ib + q * 16;
            int e = k0 + kk;
            long widx = (long)(row0 + i) * EMB + (e < EMB ? e : EMB - 1);
            Ws[i][kk] = Wih[widx];
            Xs[i][kk] = (e < EMB) ? emb[(long)toks[i] * EMB + e] : 0.f;
        }
        __syncthreads();
#pragma unroll
        for (int k = 0; k < TK; k++) {
            float a[4], x[4];
#pragma unroll
            for (int i = 0; i < 4; i++) a[i] = Ws[tx * 4 + i][k];
#pragma unroll
            for (int j = 0; j < 4; j++) x[j] = Xs[ty * 4 + j][k];
#pragma unroll
            for (int i = 0; i < 4; i++)
#pragma unroll
                for (int j = 0; j < 4; j++)
                    acc[i][j] += a[i] * x[j];
        }
        __syncthreads();
    }

#pragma unroll
    for (int i = 0; i < 4; i++) {
        int row = row0 + tx * 4 + i;
        float bias = bih[row] + bhh[row];
        int u = row & 511, g = row >> 9;
#pragma unroll
        for (int j = 0; j < 4; j++) {
            int t = t0 + ty * 4 + j;
            g_xg4[(long)t * G4 + u * 4 + g] = acc[i][j] + bias;   // [t][u][gate]
        }
    }
}

// ---------------------------------------------------------------------------
// packed fp32x2 FMA (sm_103a; only via PTX)
// ---------------------------------------------------------------------------
__device__ __forceinline__ void ffma2(unsigned long long& d,
                                      unsigned long long a, unsigned long long b)
{
    asm("fma.rn.f32x2 %0, %1, %2, %3;" : "=l"(d) : "l"(a), "l"(b), "l"(d));
}

__device__ __forceinline__ float fast_tanh(float x)
{
    float a = fabsf(x);
    float e = __expf(-2.f * a);
    float r = __fdividef(1.f - e, 1.f + e);
    return copysignf(r, x);
}
__device__ __forceinline__ float fast_sigmoid(float x)
{
    return __fdividef(1.f, 1.f + __expf(-x));
}

// ---------------------------------------------------------------------------
// Kernel 2: persistent LSTM recurrence — R4 skeleton with the publisher
// moved to WARP 7 and the trailing barrier removed.
//
// 64 CTAs x 256 threads. Warp w computes gate (w>>1), rows 4(w&1)..+3 for
// units b*8..b*8+7 (R4 layout: 8 LDS.64 + 32 ffma2 per thread, coalesced
// weights in regs). Lane 0 writes 4 sums to gates_s; bar2; then WARP 7
// lanes 0-7 do nonlinearity + ONE coalesced 64B tagged publish.
//
// Why warp 7: the SMSP arbiter is hi-wid-first. R8 showed that low-wid
// publishers get starved by spinning high-wid warps (1722us); R4's bar3
// fixed that by parking spinners (1059us). Making the publisher the
// HIGHEST warp protects its tail by priority, so bar3 can be dropped and
// warps 0-6 overlap their next-step poll with the publish tail.
//
// Race-freedom without bar3: a warp detects step-t tags only after every
// CTA's warp 7 passed bar2(t) and published — transitively, all warps of
// this CTA finished their h_s/gates_s reads for step t, so single-buffered
// smem is safe to overwrite.
// ---------------------------------------------------------------------------
// smem h layout: h[k] at f(k) = 18*(k>>4) + (k&15)  (max 573 -> 576)
__global__ __launch_bounds__(TPB, 1) void lstm_kernel(
    const int* __restrict__ tokens,
    const float* __restrict__ h0,
    const float* __restrict__ c0,
    const float* __restrict__ Whh,
    float* __restrict__ out)
{
    __shared__ __align__(16) float h_s[576];
    __shared__ float gates_s[32];
    __shared__ int   toks[SEQL];

    const int b    = blockIdx.x;
    const int tid  = threadIdx.x;
    const int w    = tid >> 5;
    const int lane = tid & 31;
    const bool is_pub = (tid >= 224 && tid < 232);   // warp 7, lanes 0-7
    const int pu   = tid - 224;                      // publisher's unit index

    for (int i = tid; i < SEQL; i += TPB) toks[i] = tokens[i];

    // Weights: warp w -> gate g=w>>1, rows rbase..rbase+3; lane covers
    // K in [16*lane, 16*lane+16) as 8 f32x2 pairs.
    const int rbase = (w >> 1) * H + b * 8 + 4 * (w & 1);
    unsigned long long wp[4][8];
#pragma unroll
    for (int i = 0; i < 4; i++) {
        const float* wrow = Whh + (size_t)(rbase + i) * H + 16 * lane;
#pragma unroll
        for (int j = 0; j < 8; j++) {
            float2 f = *(const float2*)(wrow + 2 * j);
            unsigned long long v;
            asm("mov.b64 %0, {%1,%2};" : "=l"(v) : "f"(f.x), "f"(f.y));
            wp[i][j] = v;
        }
    }

    float c_reg = 0.f, h_last = 0.f, out_reg = 0.f;
    if (is_pub) {
        c_reg  = c0[b * 8 + pu];
        h_last = h0[b * 8 + pu];
    }

    unsigned long long* htag = g_htag;

    for (int t = 0; t < SEQL; t++) {
        // Publisher threads prefetch their 4 gate biases (1 LDG.128),
        // latency hidden behind the poll below.
        float4 xgv = make_float4(0.f, 0.f, 0.f, 0.f);
        if (is_pub)
            xgv = *(const float4*)(g_xg4 + (size_t)t * G4 + (b * 8 + pu) * 4);

        // Acquire h_{t-1} into padded smem (thread handles k0=2tid, k0+1).
        {
            const int k0 = 2 * tid;
            float* dst = &h_s[18 * (k0 >> 4) + (k0 & 15)];
            if (t == 0) {
                *(float2*)dst = *(const float2*)(h0 + k0);
            } else {
                const unsigned long long* ptr =
                    htag + (size_t)(t - 1) * H + k0;
                unsigned long long v0, v1;
                const unsigned tag = (unsigned)t;
                do {
                    asm volatile("ld.volatile.global.v2.u64 {%0,%1},[%2];"
                                 : "=l"(v0), "=l"(v1) : "l"(ptr));
                } while ((unsigned)(v0 >> 32) != tag ||
                         (unsigned)(v1 >> 32) != tag);
                float2 hv;
                hv.x = __uint_as_float((unsigned)v0);
                hv.y = __uint_as_float((unsigned)v1);
                *(float2*)dst = hv;
            }
        }
        __syncthreads();                              // bar1

        // Dot: 4 gate rows x 16 K per thread, f32x2 FMAs, weights in regs.
        unsigned long long a0 = 0ull, a1 = 0ull, a2 = 0ull, a3 = 0ull;
        const unsigned long long* hb =
            (const unsigned long long*)&h_s[18 * lane];
#pragma unroll
        for (int j = 0; j < 8; j++) {
            unsigned long long hv = hb[j];            // h[16*lane+2j], h[+1]
            ffma2(a0, wp[0][j], hv);
            ffma2(a1, wp[1][j], hv);
            ffma2(a2, wp[2][j], hv);
            ffma2(a3, wp[3][j], hv);
        }
        float acc0, acc1, acc2, acc3;
        {
            float lo, hi;
            asm("mov.b64 {%0,%1}, %2;" : "=f"(lo), "=f"(hi) : "l"(a0)); acc0 = lo + hi;
            asm("mov.b64 {%0,%1}, %2;" : "=f"(lo), "=f"(hi) : "l"(a1)); acc1 = lo + hi;
            asm("mov.b64 {%0,%1}, %2;" : "=f"(lo), "=f"(hi) : "l"(a2)); acc2 = lo + hi;
            asm("mov.b64 {%0,%1}, %2;" : "=f"(lo), "=f"(hi) : "l"(a3)); acc3 = lo + hi;
        }
#pragma unroll
        for (int off = 16; off > 0; off >>= 1) {
            acc0 += __shfl_xor_sync(0xffffffffu, acc0, off);
            acc1 += __shfl_xor_sync(0xffffffffu, acc1, off);
            acc2 += __shfl_xor_sync(0xffffffffu, acc2, off);
            acc3 += __shfl_xor_sync(0xffffffffu, acc3, off);
        }
        if (lane == 0) {
            gates_s[w * 4 + 0] = acc0;
            gates_s[w * 4 + 1] = acc1;
            gates_s[w * 4 + 2] = acc2;
            gates_s[w * 4 + 3] = acc3;
        }
        __syncthreads();                              // bar2

        // Warp-7 tail: nonlinearity + ONE coalesced tagged publish.
        // (gates for unit k: gates_s[k], [8+k], [16+k], [24+k])
        if (is_pub) {
            const int k = pu;
            float si = fast_sigmoid(gates_s[k]      + xgv.x);
            float sf = fast_sigmoid(gates_s[8 + k]  + xgv.y);
            float tg = fast_tanh   (gates_s[16 + k] + xgv.z);
            float so = fast_sigmoid(gates_s[24 + k] + xgv.w);
            float c_new = sf * c_reg + si * tg;
            float h_new = so * fast_tanh(c_new);
            if (toks[t] != 1) {                 // PAD_IDX == 1
                c_reg  = c_new;
                h_last = h_new;
                out_reg = h_new;
            }
            unsigned long long v =
                ((unsigned long long)(unsigned)(t + 1) << 32) |
                (unsigned long long)__float_as_uint(h_last);
            htag[(size_t)t * H + b * 8 + k] = v;
        }
        // no bar3: publisher is the highest warp (arbiter priority) and
        // detection at t+1 transitively orders all smem reuse (see header).
    }

    if (is_pub) {
        out[b * 8 + pu]         = out_reg;  // out
        out[H + b * 8 + pu]     = h_last;   // h
        out[2 * H + b * 8 + pu] = c_reg;    // c
    }
}

extern "C" void kernel_launch(void* const* d_in, const int* in_sizes, int n_in,
                              void* d_out, int out_size)
{
    const int*   tokens = (const int*)  d_in[0];
    const float* h0     = (const float*)d_in[1];
    const float* c0     = (const float*)d_in[2];
    const float* emb    = (const float*)d_in[3];
    const float* Wih    = (const float*)d_in[4];
    const float* Whh    = (const float*)d_in[5];
    const float* bih    = (const float*)d_in[6];
    const float* bhh    = (const float*)d_in[7];
    float* out = (float*)d_out;

    // Reset the tag buffer every launch (deterministic across graph replays).
    void* htag_ptr = nullptr;
    cudaGetSymbolAddress(&htag_ptr, g_htag);
    cudaMemsetAsync(htag_ptr, 0, sizeof(unsigned long long) * SEQL * H);

    dim3 g1(G4 / 64, SEQL / 64);
    xgemm_kernel<<<g1, 256>>>(tokens, emb, Wih, bih, bhh);
    lstm_kernel<<<NCTA, TPB>>>(tokens, h0, c0, Whh, out);
}